// round 3
// baseline (speedup 1.0000x reference)
#include <cuda_runtime.h>
#include <cstdint>

#define NN 50000
#define D  128
#define KDIM 256
#define BM 128
#define BK 32

// Scratch: __device__ globals (no allocation allowed).
__device__ __align__(128) float g_agg[(size_t)NN * D];
__device__ __align__(128) float g_h1 [(size_t)NN * D];
__device__ __align__(128) float g_deg[NN];
__device__ int g_is64;   // 1 if edge_index is int64, 0 if int32

// ---------------------------------------------------------------------------
// Detect edge_index dtype. If stored as little-endian int64 with values
// < 2^31, every odd 32-bit word is 0. As int32, odd slots hold random node
// ids (all-zero over 4096 slots is impossible for this data).
// Single block; deterministic.
// ---------------------------------------------------------------------------
__global__ void k_detect(const int* __restrict__ ei32, int n32) {
    __shared__ int any_nz;
    if (threadIdx.x == 0) any_nz = 0;
    __syncthreads();
    int limit = n32 < 8192 ? n32 : 8192;
    int found = 0;
    for (int i = threadIdx.x * 2 + 1; i < limit; i += blockDim.x * 2)
        if (ei32[i] != 0) { found = 1; break; }
    if (found) atomicOr(&any_nz, 1);
    __syncthreads();
    if (threadIdx.x == 0) g_is64 = any_nz ? 0 : 1;
}

__device__ __forceinline__ int edge_idx(const void* base, int i) {
    if (g_is64) return (int)((const long long*)base)[i];
    return ((const int*)base)[i];
}

// ---------------------------------------------------------------------------
// Zero scratch. zero_deg=1 also clears the degree array.
// ---------------------------------------------------------------------------
__global__ void k_zero(int zero_deg) {
    long long stride = (long long)gridDim.x * blockDim.x;
    long long tot4 = (long long)NN * D / 4;
    float4* a4 = reinterpret_cast<float4*>(g_agg);
    for (long long i = (long long)blockIdx.x * blockDim.x + threadIdx.x;
         i < tot4; i += stride)
        a4[i] = make_float4(0.f, 0.f, 0.f, 0.f);
    if (zero_deg) {
        for (long long i = (long long)blockIdx.x * blockDim.x + threadIdx.x;
             i < NN; i += stride)
            g_deg[i] = 0.f;
    }
}

// ---------------------------------------------------------------------------
// Degree count: one reduction per edge. dstv = pointer to start of dst row.
// ---------------------------------------------------------------------------
__global__ void k_deg(const void* __restrict__ ei, int E) {
    int e = blockIdx.x * blockDim.x + threadIdx.x;
    if (e < E) {
        int d = edge_idx(ei, E + e);    // dst row is second half
        float* p = &g_deg[d];
        asm volatile("red.global.add.f32 [%0], %1;" :: "l"(p), "f"(1.0f) : "memory");
    }
}

// ---------------------------------------------------------------------------
// Scatter-aggregate: one warp per edge; each lane moves one float4 (128
// floats per edge). red.global.add.v4.f32 quarters L2 atomic-op count vs
// scalar atomicAdd.
// ---------------------------------------------------------------------------
__global__ void k_scatter(const float* __restrict__ feat,
                          const void* __restrict__ ei,
                          int E, int use_h1) {
    long long t = (long long)blockIdx.x * blockDim.x + threadIdx.x;
    int e = (int)(t >> 5);
    if (e >= E) return;
    int lane = (int)(t & 31);
    const float* f = use_h1 ? g_h1 : feat;   // device-side symbol resolution
    int s = edge_idx(ei, e);
    int d = edge_idx(ei, E + e);
    float4 v = reinterpret_cast<const float4*>(f + (size_t)s * D)[lane];
    float* p = g_agg + (size_t)d * D + lane * 4;
    asm volatile("red.global.add.v4.f32 [%0], {%1, %2, %3, %4};"
                 :: "l"(p), "f"(v.x), "f"(v.y), "f"(v.z), "f"(v.w) : "memory");
}

// ---------------------------------------------------------------------------
// Fused SAGE GEMM: out = relu( (agg/deg) @ Wl + x @ Wr + b )
// One [N,256] @ [256,128] GEMM with concatenated A = [mean | x_or_h1] and
// W = [Wl ; Wr]. BM=128 rows per block, 128 output cols, BK=32, 8x8 register
// tiles, 256 threads. in_from_h1 / out_to_h1 resolve g_h1 inside device code.
// ---------------------------------------------------------------------------
__global__ __launch_bounds__(256) void k_gemm(
    const float* __restrict__ xin,
    const float* __restrict__ Wl,
    const float* __restrict__ Wr,
    const float* __restrict__ bias,
    float* __restrict__ outbuf,
    int in_from_h1, int out_to_h1)
{
    __shared__ __align__(16) float As[BK][BM + 4];
    __shared__ __align__(16) float Bs[BK][D];

    const int tid = threadIdx.x;
    const int tr = tid >> 4;
    const int tc = tid & 15;
    const int rowBase = blockIdx.x * BM;
    const float* xsrc = in_from_h1 ? g_h1 : xin;

    float acc[8][8];
#pragma unroll
    for (int i = 0; i < 8; i++)
#pragma unroll
        for (int j = 0; j < 8; j++) acc[i][j] = 0.f;

    for (int kb = 0; kb < KDIM / BK; kb++) {
        const int k0 = kb * BK;
#pragma unroll
        for (int it = 0; it < 4; it++) {
            int lin = tid + it * 256;
            int row = lin >> 3;
            int k4  = (lin & 7) * 4;
            int grow = rowBase + row;
            float4 v = make_float4(0.f, 0.f, 0.f, 0.f);
            if (grow < NN) {
                int kg = k0 + k4;
                if (kg < D) {
                    v = *reinterpret_cast<const float4*>(&g_agg[(size_t)grow * D + kg]);
                    float inv = 1.0f / fmaxf(g_deg[grow], 1.0f);
                    v.x *= inv; v.y *= inv; v.z *= inv; v.w *= inv;
                } else {
                    v = *reinterpret_cast<const float4*>(&xsrc[(size_t)grow * D + (kg - D)]);
                }
            }
            As[k4 + 0][row] = v.x;
            As[k4 + 1][row] = v.y;
            As[k4 + 2][row] = v.z;
            As[k4 + 3][row] = v.w;
        }
#pragma unroll
        for (int it = 0; it < 4; it++) {
            int lin = tid + it * 256;
            int kk = lin >> 5;
            int c4 = (lin & 31) * 4;
            int kg = k0 + kk;
            const float* wsrc = (kg < D) ? (Wl + (size_t)kg * D + c4)
                                         : (Wr + (size_t)(kg - D) * D + c4);
            *reinterpret_cast<float4*>(&Bs[kk][c4]) =
                *reinterpret_cast<const float4*>(wsrc);
        }
        __syncthreads();

#pragma unroll
        for (int kk = 0; kk < BK; kk++) {
            float4 a0 = *reinterpret_cast<const float4*>(&As[kk][tr * 8]);
            float4 a1 = *reinterpret_cast<const float4*>(&As[kk][tr * 8 + 4]);
            float4 b0 = *reinterpret_cast<const float4*>(&Bs[kk][tc * 8]);
            float4 b1 = *reinterpret_cast<const float4*>(&Bs[kk][tc * 8 + 4]);
            float a[8] = {a0.x, a0.y, a0.z, a0.w, a1.x, a1.y, a1.z, a1.w};
            float b[8] = {b0.x, b0.y, b0.z, b0.w, b1.x, b1.y, b1.z, b1.w};
#pragma unroll
            for (int i = 0; i < 8; i++)
#pragma unroll
                for (int j = 0; j < 8; j++)
                    acc[i][j] = fmaf(a[i], b[j], acc[i][j]);
        }
        __syncthreads();
    }

    float* o = out_to_h1 ? g_h1 : outbuf;
    float bb[8];
#pragma unroll
    for (int j = 0; j < 8; j++) bb[j] = bias[tc * 8 + j];
#pragma unroll
    for (int i = 0; i < 8; i++) {
        int grow = rowBase + tr * 8 + i;
        if (grow < NN) {
            float4 r0, r1;
            r0.x = fmaxf(acc[i][0] + bb[0], 0.f);
            r0.y = fmaxf(acc[i][1] + bb[1], 0.f);
            r0.z = fmaxf(acc[i][2] + bb[2], 0.f);
            r0.w = fmaxf(acc[i][3] + bb[3], 0.f);
            r1.x = fmaxf(acc[i][4] + bb[4], 0.f);
            r1.y = fmaxf(acc[i][5] + bb[5], 0.f);
            r1.z = fmaxf(acc[i][6] + bb[6], 0.f);
            r1.w = fmaxf(acc[i][7] + bb[7], 0.f);
            *reinterpret_cast<float4*>(&o[(size_t)grow * D + tc * 8])     = r0;
            *reinterpret_cast<float4*>(&o[(size_t)grow * D + tc * 8 + 4]) = r1;
        }
    }
}

// ---------------------------------------------------------------------------
// kernel_launch: detect -> zero -> deg -> scatter1 -> gemm1 -> zero ->
//                scatter2 -> gemm2
// ---------------------------------------------------------------------------
extern "C" void kernel_launch(void* const* d_in, const int* in_sizes, int n_in,
                              void* d_out, int out_size) {
    const float* x   = (const float*)d_in[0];
    const void*  ei  = d_in[1];
    const float* W1l = (const float*)d_in[2];
    const float* b1  = (const float*)d_in[3];
    const float* W1r = (const float*)d_in[4];
    const float* W2l = (const float*)d_in[5];
    const float* b2  = (const float*)d_in[6];
    const float* W2r = (const float*)d_in[7];
    float*       out = (float*)d_out;

    const int E = in_sizes[1] / 2;

    const int gemmBlocks = (NN + BM - 1) / BM;
    const long long sthreads = (long long)E * 32;
    const int sblocks = (int)((sthreads + 255) / 256);

    k_detect<<<1, 256>>>((const int*)ei, in_sizes[1]);

    // Layer 1
    k_zero<<<2048, 256>>>(1);
    k_deg<<<(E + 255) / 256, 256>>>(ei, E);
    k_scatter<<<sblocks, 256>>>(x, ei, E, 0);
    k_gemm<<<gemmBlocks, 256>>>(x, W1l, W1r, b1, out, 0, 1);   // -> g_h1

    // Layer 2
    k_zero<<<2048, 256>>>(0);
    k_scatter<<<sblocks, 256>>>(x /*unused*/, ei, E, 1);       // reads g_h1
    k_gemm<<<gemmBlocks, 256>>>(x /*unused*/, W2l, W2r, b2, out, 1, 0);  // -> d_out
}

// round 4
// speedup vs baseline: 1.3865x; 1.3865x over previous
#include <cuda_runtime.h>
#include <cstdint>

#define NN 50000
#define D  128
#define KDIM 256
#define BM 128
#define EMAX 640000

// Scratch: __device__ globals (no allocation allowed).
__device__ __align__(128) float g_agg[(size_t)NN * D];
__device__ __align__(128) float g_h1 [(size_t)NN * D];
__device__ __align__(128) float g_deg[NN];        // becomes 1/max(deg,1)
__device__ __align__(128) int   g_src[EMAX];
__device__ __align__(128) int   g_dst[EMAX];
__device__ int g_is64;

// ---------------------------------------------------------------------------
// Detect edge_index dtype: int64 node ids < 2^31 have all odd 32-bit words 0.
// ---------------------------------------------------------------------------
__global__ void k_detect(const int* __restrict__ ei32, int n32) {
    __shared__ int any_nz;
    if (threadIdx.x == 0) any_nz = 0;
    __syncthreads();
    int limit = n32 < 8192 ? n32 : 8192;
    int found = 0;
    for (int i = threadIdx.x * 2 + 1; i < limit; i += blockDim.x * 2)
        if (ei32[i] != 0) { found = 1; break; }
    if (found) atomicOr(&any_nz, 1);
    __syncthreads();
    if (threadIdx.x == 0) g_is64 = any_nz ? 0 : 1;
}

// Decode edge list once into int32 scratch (reused by both layers).
__global__ void k_decode(const void* __restrict__ ei, int E) {
    int e = blockIdx.x * blockDim.x + threadIdx.x;
    if (e >= E) return;
    if (g_is64) {
        g_src[e] = (int)((const long long*)ei)[e];
        g_dst[e] = (int)((const long long*)ei)[E + e];
    } else {
        g_src[e] = ((const int*)ei)[e];
        g_dst[e] = ((const int*)ei)[E + e];
    }
}

// ---------------------------------------------------------------------------
// Zero scratch. zero_deg=1 also clears the degree array.
// ---------------------------------------------------------------------------
__global__ void k_zero(int zero_deg) {
    long long stride = (long long)gridDim.x * blockDim.x;
    long long tot4 = (long long)NN * D / 4;
    float4* a4 = reinterpret_cast<float4*>(g_agg);
    for (long long i = (long long)blockIdx.x * blockDim.x + threadIdx.x;
         i < tot4; i += stride)
        a4[i] = make_float4(0.f, 0.f, 0.f, 0.f);
    if (zero_deg) {
        for (long long i = (long long)blockIdx.x * blockDim.x + threadIdx.x;
             i < NN; i += stride)
            g_deg[i] = 0.f;
    }
}

__global__ void k_deg(int E) {
    int e = blockIdx.x * blockDim.x + threadIdx.x;
    if (e < E) {
        float* p = &g_deg[g_dst[e]];
        asm volatile("red.global.add.f32 [%0], %1;" :: "l"(p), "f"(1.0f) : "memory");
    }
}

__global__ void k_invdeg() {
    int i = blockIdx.x * blockDim.x + threadIdx.x;
    if (i < NN) g_deg[i] = 1.0f / fmaxf(g_deg[i], 1.0f);
}

// ---------------------------------------------------------------------------
// Scatter-aggregate: one warp per edge; red.global.add.v4.f32.
// ---------------------------------------------------------------------------
__global__ void k_scatter(const float* __restrict__ feat, int E, int use_h1) {
    long long t = (long long)blockIdx.x * blockDim.x + threadIdx.x;
    int e = (int)(t >> 5);
    if (e >= E) return;
    int lane = (int)(t & 31);
    const float* f = use_h1 ? g_h1 : feat;
    int s = g_src[e];
    int d = g_dst[e];
    float4 v = reinterpret_cast<const float4*>(f + (size_t)s * D)[lane];
    float* p = g_agg + (size_t)d * D + lane * 4;
    asm volatile("red.global.add.v4.f32 [%0], {%1, %2, %3, %4};"
                 :: "l"(p), "f"(v.x), "f"(v.y), "f"(v.z), "f"(v.w) : "memory");
}

// ---------------------------------------------------------------------------
// tf32 tensor-core fused SAGE GEMM:
//   out = relu( (agg * invdeg) @ Wl + x @ Wr + b )
// One [N,256]x[256,128] GEMM, A = [mean | x_or_h1], W = [Wl ; Wr].
// BM=128 rows/block, BN=128 (full), BK=16, 8 warps: warp tile 64x32
// (4 m16 x 4 n8 mma tiles per k-step, 2 k-steps of k8 per k-block).
// A/B staged K-contiguous with stride 20 floats: fragment LDS pattern
// (row*20 + k) hits all 32 banks (conflict-free).
// ---------------------------------------------------------------------------
__device__ __forceinline__ uint32_t to_tf32(float f) {
    uint32_t r;
    asm("cvt.rna.tf32.f32 %0, %1;" : "=r"(r) : "f"(f));
    return r;
}

__global__ __launch_bounds__(256) void k_gemm(
    const float* __restrict__ xin,
    const float* __restrict__ Wl,
    const float* __restrict__ Wr,
    const float* __restrict__ bias,
    float* __restrict__ outbuf,
    int in_from_h1, int out_to_h1)
{
    __shared__ uint32_t As[128][20];   // As[row][k] (tf32 bits)
    __shared__ uint32_t Bs[128][20];   // Bs[col][k] (tf32 bits)

    const int tid  = threadIdx.x;
    const int wid  = tid >> 5;
    const int lane = tid & 31;
    const int grp  = lane >> 2;    // 0..7
    const int tig  = lane & 3;     // 0..3
    const int warpRow = (wid >> 2) * 64;   // 0 or 64
    const int warpCol = (wid & 3) * 32;    // 0,32,64,96
    const int rowBase = blockIdx.x * BM;
    const float* xsrc = in_from_h1 ? g_h1 : xin;

    float acc[4][4][4];
#pragma unroll
    for (int mt = 0; mt < 4; mt++)
#pragma unroll
        for (int nt = 0; nt < 4; nt++)
#pragma unroll
            for (int q = 0; q < 4; q++) acc[mt][nt][q] = 0.f;

    // A-staging thread map: 2 threads per row, 8 k each.
    const int arow  = tid >> 1;
    const int akloc = (tid & 1) * 8;

    for (int kb = 0; kb < KDIM / 16; kb++) {
        const int k0 = kb * 16;

        // ---- stage A (128 rows x 16 k)
        {
            int grow = rowBase + arow;
            float v[8];
            if (grow < NN) {
                int kg = k0 + akloc;
                if (k0 < D) {
                    const float4* p = reinterpret_cast<const float4*>(
                        &g_agg[(size_t)grow * D + kg]);
                    float inv = g_deg[grow];
                    float4 u0 = p[0], u1 = p[1];
                    v[0]=u0.x*inv; v[1]=u0.y*inv; v[2]=u0.z*inv; v[3]=u0.w*inv;
                    v[4]=u1.x*inv; v[5]=u1.y*inv; v[6]=u1.z*inv; v[7]=u1.w*inv;
                } else {
                    const float4* p = reinterpret_cast<const float4*>(
                        &xsrc[(size_t)grow * D + (kg - D)]);
                    float4 u0 = p[0], u1 = p[1];
                    v[0]=u0.x; v[1]=u0.y; v[2]=u0.z; v[3]=u0.w;
                    v[4]=u1.x; v[5]=u1.y; v[6]=u1.z; v[7]=u1.w;
                }
            } else {
#pragma unroll
                for (int j = 0; j < 8; j++) v[j] = 0.f;
            }
            uint2* dstp = reinterpret_cast<uint2*>(&As[arow][akloc]);
#pragma unroll
            for (int j = 0; j < 4; j++)
                dstp[j] = make_uint2(to_tf32(v[2*j]), to_tf32(v[2*j+1]));
        }

        // ---- stage B transposed: Bs[col][k] from W[k][col]
#pragma unroll
        for (int it = 0; it < 2; it++) {
            int lin = tid + it * 256;        // 0..511
            int kk  = lin >> 5;              // 0..15
            int c4  = (lin & 31) * 4;        // 0..124
            int kg  = k0 + kk;
            const float* wsrc = (kg < D) ? (Wl + (size_t)kg * D + c4)
                                         : (Wr + (size_t)(kg - D) * D + c4);
            float4 u = *reinterpret_cast<const float4*>(wsrc);
            Bs[c4 + 0][kk] = to_tf32(u.x);
            Bs[c4 + 1][kk] = to_tf32(u.y);
            Bs[c4 + 2][kk] = to_tf32(u.z);
            Bs[c4 + 3][kk] = to_tf32(u.w);
        }
        __syncthreads();

        // ---- compute: 2 k-steps of m16n8k8
#pragma unroll
        for (int ks = 0; ks < 2; ks++) {
            const int kb8 = ks * 8;
            uint32_t a[4][4], b[4][2];
#pragma unroll
            for (int mt = 0; mt < 4; mt++) {
                int r0 = warpRow + mt * 16;
                a[mt][0] = As[r0 + grp    ][kb8 + tig];
                a[mt][1] = As[r0 + grp + 8][kb8 + tig];
                a[mt][2] = As[r0 + grp    ][kb8 + tig + 4];
                a[mt][3] = As[r0 + grp + 8][kb8 + tig + 4];
            }
#pragma unroll
            for (int nt = 0; nt < 4; nt++) {
                int cn = warpCol + nt * 8 + grp;
                b[nt][0] = Bs[cn][kb8 + tig];
                b[nt][1] = Bs[cn][kb8 + tig + 4];
            }
#pragma unroll
            for (int mt = 0; mt < 4; mt++)
#pragma unroll
                for (int nt = 0; nt < 4; nt++) {
                    asm volatile(
                        "mma.sync.aligned.m16n8k8.row.col.f32.tf32.tf32.f32 "
                        "{%0,%1,%2,%3}, {%4,%5,%6,%7}, {%8,%9}, {%0,%1,%2,%3};\n"
                        : "+f"(acc[mt][nt][0]), "+f"(acc[mt][nt][1]),
                          "+f"(acc[mt][nt][2]), "+f"(acc[mt][nt][3])
                        : "r"(a[mt][0]), "r"(a[mt][1]), "r"(a[mt][2]), "r"(a[mt][3]),
                          "r"(b[nt][0]), "r"(b[nt][1]));
                }
        }
        __syncthreads();
    }

    // ---- epilogue: + bias, relu, store
    float* o = out_to_h1 ? g_h1 : outbuf;
#pragma unroll
    for (int nt = 0; nt < 4; nt++) {
        int c = warpCol + nt * 8 + 2 * tig;
        float b0 = bias[c], b1 = bias[c + 1];
#pragma unroll
        for (int mt = 0; mt < 4; mt++) {
            int r = rowBase + warpRow + mt * 16 + grp;
            if (r < NN) {
                float2 v;
                v.x = fmaxf(acc[mt][nt][0] + b0, 0.f);
                v.y = fmaxf(acc[mt][nt][1] + b1, 0.f);
                *reinterpret_cast<float2*>(&o[(size_t)r * D + c]) = v;
            }
            if (r + 8 < NN) {
                float2 v;
                v.x = fmaxf(acc[mt][nt][2] + b0, 0.f);
                v.y = fmaxf(acc[mt][nt][3] + b1, 0.f);
                *reinterpret_cast<float2*>(&o[(size_t)(r + 8) * D + c]) = v;
            }
        }
    }
}

// ---------------------------------------------------------------------------
extern "C" void kernel_launch(void* const* d_in, const int* in_sizes, int n_in,
                              void* d_out, int out_size) {
    const float* x   = (const float*)d_in[0];
    const void*  ei  = d_in[1];
    const float* W1l = (const float*)d_in[2];
    const float* b1  = (const float*)d_in[3];
    const float* W1r = (const float*)d_in[4];
    const float* W2l = (const float*)d_in[5];
    const float* b2  = (const float*)d_in[6];
    const float* W2r = (const float*)d_in[7];
    float*       out = (float*)d_out;

    const int E = in_sizes[1] / 2;

    const int gemmBlocks = (NN + BM - 1) / BM;
    const long long sthreads = (long long)E * 32;
    const int sblocks = (int)((sthreads + 255) / 256);
    const int eblocks = (E + 255) / 256;

    k_detect<<<1, 256>>>((const int*)ei, in_sizes[1]);
    k_decode<<<eblocks, 256>>>(ei, E);

    // Layer 1
    k_zero<<<2048, 256>>>(1);
    k_deg<<<eblocks, 256>>>(E);
    k_invdeg<<<(NN + 255) / 256, 256>>>();
    k_scatter<<<sblocks, 256>>>(x, E, 0);
    k_gemm<<<gemmBlocks, 256>>>(x, W1l, W1r, b1, out, 0, 1);   // -> g_h1

    // Layer 2
    k_zero<<<2048, 256>>>(0);
    k_scatter<<<sblocks, 256>>>(x /*unused*/, E, 1);           // reads g_h1
    k_gemm<<<gemmBlocks, 256>>>(x /*unused*/, W2l, W2r, b2, out, 1, 0);
}

// round 5
// speedup vs baseline: 1.9038x; 1.3731x over previous
#include <cuda_runtime.h>
#include <cstdint>

#define NN 50000
#define D  128
#define KDIM 256
#define BM 128
#define EMAX 640000
#define SCAN_BLOCKS 196   // ceil(50000/256)

// Scratch: __device__ globals (no allocation allowed).
__device__ __align__(128) float g_agg[(size_t)NN * D];   // holds MEAN after gather
__device__ __align__(128) float g_h1 [(size_t)NN * D];
__device__ __align__(128) int   g_src[EMAX];
__device__ __align__(128) int   g_dst[EMAX];
__device__ __align__(128) int   g_cnt[NN];        // histogram, then fill cursor
__device__ __align__(128) int   g_rowptr[NN + 1];
__device__ __align__(128) int   g_col[EMAX];      // src ids grouped by dst
__device__ __align__(128) int   g_bsum[256];
__device__ int g_is64;

// ---------------------------------------------------------------------------
// Detect edge_index dtype: int64 node ids < 2^31 have all odd 32-bit words 0.
// ---------------------------------------------------------------------------
__global__ void k_detect(const int* __restrict__ ei32, int n32) {
    __shared__ int any_nz;
    if (threadIdx.x == 0) any_nz = 0;
    __syncthreads();
    int limit = n32 < 8192 ? n32 : 8192;
    int found = 0;
    for (int i = threadIdx.x * 2 + 1; i < limit; i += blockDim.x * 2)
        if (ei32[i] != 0) { found = 1; break; }
    if (found) atomicOr(&any_nz, 1);
    __syncthreads();
    if (threadIdx.x == 0) g_is64 = any_nz ? 0 : 1;
}

// Decode edge list once into int32 scratch, zero histogram.
__global__ void k_decode(const void* __restrict__ ei, int E) {
    int e = blockIdx.x * blockDim.x + threadIdx.x;
    if (e < NN) g_cnt[e] = 0;            // E > NN, reuse grid to zero histogram
    if (e >= E) return;
    if (g_is64) {
        g_src[e] = (int)((const long long*)ei)[e];
        g_dst[e] = (int)((const long long*)ei)[E + e];
    } else {
        g_src[e] = ((const int*)ei)[e];
        g_dst[e] = ((const int*)ei)[E + e];
    }
}

__global__ void k_hist(int E) {
    int e = blockIdx.x * blockDim.x + threadIdx.x;
    if (e < E) atomicAdd(&g_cnt[g_dst[e]], 1);
}

// Exclusive scan over g_cnt -> g_rowptr (3 stages).
__global__ void k_scan1() {
    __shared__ int sh[256];
    int gid = blockIdx.x * 256 + threadIdx.x;
    int v = (gid < NN) ? g_cnt[gid] : 0;
    sh[threadIdx.x] = v;
    __syncthreads();
    for (int off = 1; off < 256; off <<= 1) {
        int t = (threadIdx.x >= off) ? sh[threadIdx.x - off] : 0;
        __syncthreads();
        sh[threadIdx.x] += t;
        __syncthreads();
    }
    if (gid < NN) g_rowptr[gid] = sh[threadIdx.x] - v;  // exclusive within block
    if (threadIdx.x == 255) g_bsum[blockIdx.x] = sh[255];
}

__global__ void k_scan2(int nb) {
    __shared__ int sh[256];
    int v = (threadIdx.x < nb) ? g_bsum[threadIdx.x] : 0;
    sh[threadIdx.x] = v;
    __syncthreads();
    for (int off = 1; off < 256; off <<= 1) {
        int t = (threadIdx.x >= off) ? sh[threadIdx.x - off] : 0;
        __syncthreads();
        sh[threadIdx.x] += t;
        __syncthreads();
    }
    if (threadIdx.x < nb) g_bsum[threadIdx.x] = sh[threadIdx.x] - v;
}

__global__ void k_scan3(int E) {
    int gid = blockIdx.x * 256 + threadIdx.x;
    if (gid < NN) {
        int r = g_rowptr[gid] + g_bsum[blockIdx.x];
        g_rowptr[gid] = r;
        g_cnt[gid] = r;          // cursor for fill
    }
    if (gid == 0) g_rowptr[NN] = E;
}

__global__ void k_fill(int E) {
    int e = blockIdx.x * blockDim.x + threadIdx.x;
    if (e < E) {
        int idx = atomicAdd(&g_cnt[g_dst[e]], 1);
        g_col[idx] = g_src[e];
    }
}

// ---------------------------------------------------------------------------
// CSR gather-aggregate: one warp per node, lane owns one float4 slice.
// No atomics, no pre-zeroing; writes the MEAN directly.
// ---------------------------------------------------------------------------
__global__ __launch_bounds__(256) void k_gather(const float* __restrict__ feat,
                                                int use_h1) {
    int node = blockIdx.x * 8 + (threadIdx.x >> 5);
    if (node >= NN) return;
    int lane = threadIdx.x & 31;
    const float* f = use_h1 ? g_h1 : feat;
    int beg = g_rowptr[node], end = g_rowptr[node + 1];
    float4 acc = make_float4(0.f, 0.f, 0.f, 0.f);
    int j = beg;
    for (; j + 1 < end; j += 2) {
        int s0 = g_col[j], s1 = g_col[j + 1];
        float4 v0 = reinterpret_cast<const float4*>(f + (size_t)s0 * D)[lane];
        float4 v1 = reinterpret_cast<const float4*>(f + (size_t)s1 * D)[lane];
        acc.x += v0.x; acc.y += v0.y; acc.z += v0.z; acc.w += v0.w;
        acc.x += v1.x; acc.y += v1.y; acc.z += v1.z; acc.w += v1.w;
    }
    if (j < end) {
        int s0 = g_col[j];
        float4 v0 = reinterpret_cast<const float4*>(f + (size_t)s0 * D)[lane];
        acc.x += v0.x; acc.y += v0.y; acc.z += v0.z; acc.w += v0.w;
    }
    float inv = 1.0f / fmaxf((float)(end - beg), 1.0f);
    acc.x *= inv; acc.y *= inv; acc.z *= inv; acc.w *= inv;
    reinterpret_cast<float4*>(g_agg + (size_t)node * D)[lane] = acc;
}

// ---------------------------------------------------------------------------
// tf32 tensor-core fused SAGE GEMM:
//   out = relu( mean @ Wl + x @ Wr + b ),  A = [g_agg | x_or_h1], W = [Wl;Wr]
// BM=128 rows/block, BN=128, BK=16, 8 warps, warp tile 64x32.
// SMEM stride 20: fragment LDS pattern row*20+k is bank-conflict-free.
// ---------------------------------------------------------------------------
__device__ __forceinline__ uint32_t to_tf32(float f) {
    uint32_t r;
    asm("cvt.rna.tf32.f32 %0, %1;" : "=r"(r) : "f"(f));
    return r;
}

__global__ __launch_bounds__(256) void k_gemm(
    const float* __restrict__ xin,
    const float* __restrict__ Wl,
    const float* __restrict__ Wr,
    const float* __restrict__ bias,
    float* __restrict__ outbuf,
    int in_from_h1, int out_to_h1)
{
    __shared__ uint32_t As[128][20];
    __shared__ uint32_t Bs[128][20];

    const int tid  = threadIdx.x;
    const int wid  = tid >> 5;
    const int lane = tid & 31;
    const int grp  = lane >> 2;
    const int tig  = lane & 3;
    const int warpRow = (wid >> 2) * 64;
    const int warpCol = (wid & 3) * 32;
    const int rowBase = blockIdx.x * BM;
    const float* xsrc = in_from_h1 ? g_h1 : xin;

    float acc[4][4][4];
#pragma unroll
    for (int mt = 0; mt < 4; mt++)
#pragma unroll
        for (int nt = 0; nt < 4; nt++)
#pragma unroll
            for (int q = 0; q < 4; q++) acc[mt][nt][q] = 0.f;

    const int arow  = tid >> 1;
    const int akloc = (tid & 1) * 8;

    for (int kb = 0; kb < KDIM / 16; kb++) {
        const int k0 = kb * 16;

        // ---- stage A (128 rows x 16 k)
        {
            int grow = rowBase + arow;
            float v[8];
            if (grow < NN) {
                int kg = k0 + akloc;
                const float* srcp = (k0 < D)
                    ? &g_agg[(size_t)grow * D + kg]
                    : &xsrc[(size_t)grow * D + (kg - D)];
                float4 u0 = reinterpret_cast<const float4*>(srcp)[0];
                float4 u1 = reinterpret_cast<const float4*>(srcp)[1];
                v[0]=u0.x; v[1]=u0.y; v[2]=u0.z; v[3]=u0.w;
                v[4]=u1.x; v[5]=u1.y; v[6]=u1.z; v[7]=u1.w;
            } else {
#pragma unroll
                for (int j = 0; j < 8; j++) v[j] = 0.f;
            }
            uint2* dstp = reinterpret_cast<uint2*>(&As[arow][akloc]);
#pragma unroll
            for (int j = 0; j < 4; j++)
                dstp[j] = make_uint2(to_tf32(v[2*j]), to_tf32(v[2*j+1]));
        }

        // ---- stage B transposed: Bs[col][k] from W[k][col]
#pragma unroll
        for (int it = 0; it < 2; it++) {
            int lin = tid + it * 256;
            int kk  = lin >> 5;
            int c4  = (lin & 31) * 4;
            int kg  = k0 + kk;
            const float* wsrc = (kg < D) ? (Wl + (size_t)kg * D + c4)
                                         : (Wr + (size_t)(kg - D) * D + c4);
            float4 u = *reinterpret_cast<const float4*>(wsrc);
            Bs[c4 + 0][kk] = to_tf32(u.x);
            Bs[c4 + 1][kk] = to_tf32(u.y);
            Bs[c4 + 2][kk] = to_tf32(u.z);
            Bs[c4 + 3][kk] = to_tf32(u.w);
        }
        __syncthreads();

#pragma unroll
        for (int ks = 0; ks < 2; ks++) {
            const int kb8 = ks * 8;
            uint32_t a[4][4], b[4][2];
#pragma unroll
            for (int mt = 0; mt < 4; mt++) {
                int r0 = warpRow + mt * 16;
                a[mt][0] = As[r0 + grp    ][kb8 + tig];
                a[mt][1] = As[r0 + grp + 8][kb8 + tig];
                a[mt][2] = As[r0 + grp    ][kb8 + tig + 4];
                a[mt][3] = As[r0 + grp + 8][kb8 + tig + 4];
            }
#pragma unroll
            for (int nt = 0; nt < 4; nt++) {
                int cn = warpCol + nt * 8 + grp;
                b[nt][0] = Bs[cn][kb8 + tig];
                b[nt][1] = Bs[cn][kb8 + tig + 4];
            }
#pragma unroll
            for (int mt = 0; mt < 4; mt++)
#pragma unroll
                for (int nt = 0; nt < 4; nt++) {
                    asm volatile(
                        "mma.sync.aligned.m16n8k8.row.col.f32.tf32.tf32.f32 "
                        "{%0,%1,%2,%3}, {%4,%5,%6,%7}, {%8,%9}, {%0,%1,%2,%3};\n"
                        : "+f"(acc[mt][nt][0]), "+f"(acc[mt][nt][1]),
                          "+f"(acc[mt][nt][2]), "+f"(acc[mt][nt][3])
                        : "r"(a[mt][0]), "r"(a[mt][1]), "r"(a[mt][2]), "r"(a[mt][3]),
                          "r"(b[nt][0]), "r"(b[nt][1]));
                }
        }
        __syncthreads();
    }

    float* o = out_to_h1 ? g_h1 : outbuf;
#pragma unroll
    for (int nt = 0; nt < 4; nt++) {
        int c = warpCol + nt * 8 + 2 * tig;
        float b0 = bias[c], b1 = bias[c + 1];
#pragma unroll
        for (int mt = 0; mt < 4; mt++) {
            int r = rowBase + warpRow + mt * 16 + grp;
            if (r < NN) {
                float2 v;
                v.x = fmaxf(acc[mt][nt][0] + b0, 0.f);
                v.y = fmaxf(acc[mt][nt][1] + b1, 0.f);
                *reinterpret_cast<float2*>(&o[(size_t)r * D + c]) = v;
            }
            if (r + 8 < NN) {
                float2 v;
                v.x = fmaxf(acc[mt][nt][2] + b0, 0.f);
                v.y = fmaxf(acc[mt][nt][3] + b1, 0.f);
                *reinterpret_cast<float2*>(&o[(size_t)(r + 8) * D + c]) = v;
            }
        }
    }
}

// ---------------------------------------------------------------------------
// kernel_launch: detect -> decode(+zero hist) -> hist -> scan x3 -> fill ->
//                gather1 -> gemm1 -> gather2 -> gemm2
// ---------------------------------------------------------------------------
extern "C" void kernel_launch(void* const* d_in, const int* in_sizes, int n_in,
                              void* d_out, int out_size) {
    const float* x   = (const float*)d_in[0];
    const void*  ei  = d_in[1];
    const float* W1l = (const float*)d_in[2];
    const float* b1  = (const float*)d_in[3];
    const float* W1r = (const float*)d_in[4];
    const float* W2l = (const float*)d_in[5];
    const float* b2  = (const float*)d_in[6];
    const float* W2r = (const float*)d_in[7];
    float*       out = (float*)d_out;

    const int E = in_sizes[1] / 2;
    const int eblocks = (E + 255) / 256;
    const int gemmBlocks = (NN + BM - 1) / BM;
    const int gatherBlocks = (NN + 7) / 8;

    k_detect<<<1, 256>>>((const int*)ei, in_sizes[1]);
    k_decode<<<eblocks, 256>>>(ei, E);

    // CSR build
    k_hist<<<eblocks, 256>>>(E);
    k_scan1<<<SCAN_BLOCKS, 256>>>();
    k_scan2<<<1, 256>>>(SCAN_BLOCKS);
    k_scan3<<<SCAN_BLOCKS, 256>>>(E);
    k_fill<<<eblocks, 256>>>(E);

    // Layer 1
    k_gather<<<gatherBlocks, 256>>>(x, 0);
    k_gemm<<<gemmBlocks, 256>>>(x, W1l, W1r, b1, out, 0, 1);   // -> g_h1

    // Layer 2
    k_gather<<<gatherBlocks, 256>>>(x /*unused*/, 1);          // reads g_h1
    k_gemm<<<gemmBlocks, 256>>>(x /*unused*/, W2l, W2r, b2, out, 1, 0);
}